// round 15
// baseline (speedup 1.0000x reference)
#include <cuda_runtime.h>
#include <cuda_fp16.h>
#include <math.h>
#include <stdint.h>

#define BB 32
#define H0 161
#define W0 1024
#define H1 81
#define W1 512
#define H2 41
#define W2 512
#define EPSV 1e-5f

// x1 scratch: channels-last fp16 [b][h1][w][ic]
__device__ __half g_x1h[BB * H1 * W1 * 32];
// conv2 weights fp16: [kh][kw][oc][40 pad]
__device__ __half g_w2h[21 * 11 * 32 * 40];
// conv1 input, fp16, shifted rows: [b][ih][t], S[t]=in[t-5]
#define C1_ROW_H 1056
__device__ __half g_in_h[BB * H0 * C1_ROW_H];
// conv1 weights fp16: [kh][oc][18]
__device__ __half g_w1h[41 * 32 * 18];

// ---------------------------------------------------------------------------
__device__ __forceinline__ uint32_t smem_u32(const void* p) {
    uint32_t a;
    asm("{ .reg .u64 t; cvta.to.shared.u64 t, %1; cvt.u32.u64 %0, t; }"
        : "=r"(a) : "l"(p));
    return a;
}
__device__ __forceinline__ void cp16(uint32_t dst, const void* src) {
    asm volatile("cp.async.ca.shared.global [%0], [%1], 16;"
                 :: "r"(dst), "l"(src) : "memory");
}
__device__ __forceinline__ void cp_commit() {
    asm volatile("cp.async.commit_group;" ::: "memory");
}
__device__ __forceinline__ void cp_wait0() {
    asm volatile("cp.async.wait_group 0;" ::: "memory");
}
__device__ __forceinline__ void ldm_x4(uint32_t* a, uint32_t addr) {
    asm volatile("ldmatrix.sync.aligned.m8n8.x4.shared.b16 {%0,%1,%2,%3}, [%4];"
                 : "=r"(a[0]), "=r"(a[1]), "=r"(a[2]), "=r"(a[3]) : "r"(addr));
}
__device__ __forceinline__ void mma_f16(float* d, const uint32_t* a,
                                        const uint32_t* b) {
    asm volatile(
        "mma.sync.aligned.m16n8k16.row.col.f32.f16.f16.f32 "
        "{%0,%1,%2,%3}, {%4,%5,%6,%7}, {%8,%9}, {%0,%1,%2,%3};"
        : "+f"(d[0]), "+f"(d[1]), "+f"(d[2]), "+f"(d[3])
        : "r"(a[0]), "r"(a[1]), "r"(a[2]), "r"(a[3]), "r"(b[0]), "r"(b[1]));
}

// ---------------------------------------------------------------------------
// Kernel 0: merged prep (unchanged, proven).
// ---------------------------------------------------------------------------
__global__ void prep_kernel(const float* __restrict__ in,
                            const float* __restrict__ w1,
                            const float* __restrict__ w2) {
    int i = blockIdx.x * 256 + threadIdx.x;
    const int total0 = BB * H0 * C1_ROW_H;
    if (i < total0) {
        int t = i % C1_ROW_H;
        int r = i / C1_ROW_H;
        int s = t - 5;
        float v = 0.f;
        if ((unsigned)s < W0) v = in[(size_t)r * W0 + s];
        g_in_h[i] = __float2half_rn(v);
    }
    if (i < 41 * 32 * 18) {
        int k = i % 18;
        int t = i / 18;
        int oc = t & 31;
        int kh = t >> 5;
        float v = (k < 11) ? w1[oc * 451 + kh * 11 + k] : 0.f;
        g_w1h[i] = __float2half_rn(v);
    }
    if (i < 21 * 11 * 32 * 40) {
        int ic = i % 40;
        int t = i / 40;
        int oc = t & 31;
        t >>= 5;
        int kw = t % 11;
        int kh = t / 11;
        float v = (ic < 32) ? w2[((oc * 32 + ic) * 21 + kh) * 11 + kw] : 0.f;
        g_w2h[i] = __float2half_rn(v);
    }
}

// ---------------------------------------------------------------------------
// Kernel 1: conv1 fp16 mma, TWO h1 rows per CTA sharing the weight slab.
// CTA = (w-half 256px, h1 pair, b): 512 thr / 16 warps = 2 rows x 8 warps,
// mt=2/warp, 1 CTA/SM. Barrier-free mainloop (A frags straight from global).
// Dead-half CTAs zero only the first 16 px per row (conv2 reads at most
// pixel 260 past a half boundary).
// ---------------------------------------------------------------------------
#define C1_HDR 256
#define C1_W_OFF C1_HDR
#define C1_W_BYTES (41 * 32 * 18 * 2)
#define C1_SM_BYTES (C1_W_OFF + C1_W_BYTES)

__global__ void __launch_bounds__(512, 1) conv1_mma_kernel(
    const int* __restrict__ seq,
    const float* __restrict__ b1, const float* __restrict__ g1,
    const float* __restrict__ be1, const float* __restrict__ m1,
    const float* __restrict__ v1)
{
    extern __shared__ char smc[];
    uint32_t sb = smem_u32(smc);
    float* hdr = (float*)smc;
    int tid = threadIdx.x, wid = tid >> 5, lane = tid & 31;
    int gid = lane >> 2, tg = lane & 3;
    int row = wid >> 3, wseg = wid & 7;
    int w0 = blockIdx.x * 256;
    int hp = blockIdx.y, b = blockIdx.z;
    int h1r = 2 * hp + row;
    int len1 = (seq[b] - 1) / 2 + 1;
    int npix = min(256, len1 - w0);

    // Whole-CTA skip: only the 16-px halo needs zeroing (2 rows).
    if (npix <= 0) {
        // 2 rows x 16 px x 32 ic halves = 2 x 128 float4
        if (tid < 256) {
            int r = tid >> 7, j = tid & 127;
            int h1 = 2 * hp + r;
            if (h1 < H1) {
                float4* dst = (float4*)(g_x1h + ((size_t)(b * H1 + h1) * W1 + w0) * 32);
                dst[j] = make_float4(0.f, 0.f, 0.f, 0.f);
            }
        }
        return;
    }

    if (tid < 32) {
        float a = g1[tid] * rsqrtf(v1[tid] + EPSV);
        hdr[tid]      = a;
        hdr[32 + tid] = b1[tid] * a + be1[tid] - m1[tid] * a;
    }
    for (int i = tid; i < C1_W_BYTES / 16; i += 512)
        cp16(sb + C1_W_OFF + i * 16, (const char*)g_w1h + i * 16);
    cp_commit();
    cp_wait0();
    __syncthreads();   // the ONLY barrier

    float acc[2][4][4];
#pragma unroll
    for (int mt = 0; mt < 2; mt++)
#pragma unroll
        for (int nt = 0; nt < 4; nt++)
#pragma unroll
            for (int r = 0; r < 4; r++) acc[mt][nt][r] = 0.f;

    int lofs = 4 * (gid + tg);

    if (h1r < H1) {
        int khL = max(0, 20 - 2 * h1r);
        int khH = min(40, 180 - 2 * h1r);
        const char* inb =
            (const char*)(g_in_h + (size_t)(b * H0 + 2 * h1r - 20) * C1_ROW_H);

#pragma unroll 2
        for (int kh = khL; kh <= khH; kh++) {
            uint32_t bf[4][2];
            const char* wk = smc + C1_W_OFF + kh * (32 * 18 * 2);
#pragma unroll
            for (int nt = 0; nt < 4; nt++) {
                const char* q = wk + (nt * 8 + gid) * 36 + tg * 4;
                bf[nt][0] = *(const uint32_t*)q;
                bf[nt][1] = *(const uint32_t*)(q + 16);
            }
            const char* arow = inb + (size_t)kh * (C1_ROW_H * 2);
#pragma unroll
            for (int mt = 0; mt < 2; mt++) {
                int pb = wseg * 32 + mt * 16;
                if (pb >= npix) continue;
                const char* ab = arow + 4 * (w0 + pb) + lofs;
                uint32_t af[4];
                af[0] = *(const uint32_t*)(ab);
                af[1] = *(const uint32_t*)(ab + 32);
                af[2] = *(const uint32_t*)(ab + 16);
                af[3] = *(const uint32_t*)(ab + 48);
#pragma unroll
                for (int nt = 0; nt < 4; nt++)
                    mma_f16(acc[mt][nt], af, bf[nt]);
            }
        }

        const float* sa = hdr;
        const float* sc = hdr + 32;
        __half* xb = g_x1h + ((size_t)(b * H1 + h1r) * W1 + w0) * 32;
#pragma unroll
        for (int mt = 0; mt < 2; mt++) {
            int p0 = wseg * 32 + mt * 16 + gid;
            int p1 = p0 + 8;
#pragma unroll
            for (int nt = 0; nt < 4; nt++) {
                int oc0 = nt * 8 + 2 * tg;
                float a0 = sa[oc0], c0 = sc[oc0];
                float a1 = sa[oc0 + 1], c1 = sc[oc0 + 1];
                float y0 = 0.f, y1 = 0.f, y2 = 0.f, y3 = 0.f;
                if (p0 < npix) {
                    y0 = fminf(fmaxf(acc[mt][nt][0] * a0 + c0, 0.f), 20.f);
                    y1 = fminf(fmaxf(acc[mt][nt][1] * a1 + c1, 0.f), 20.f);
                }
                if (p1 < npix) {
                    y2 = fminf(fmaxf(acc[mt][nt][2] * a0 + c0, 0.f), 20.f);
                    y3 = fminf(fmaxf(acc[mt][nt][3] * a1 + c1, 0.f), 20.f);
                }
                *(__half2*)(xb + (size_t)p0 * 32 + oc0) =
                    __halves2half2(__float2half_rn(y0), __float2half_rn(y1));
                *(__half2*)(xb + (size_t)p1 * 32 + oc0) =
                    __halves2half2(__float2half_rn(y2), __float2half_rn(y3));
            }
        }
    }
}

// ---------------------------------------------------------------------------
// Kernel 2: conv2 fp16 mma, TWO h2 rows per CTA (proven fastest shape,
// byte-identical to the 678us build).
// ---------------------------------------------------------------------------
#define HDR_B 256
#define A_STRIDE_B 80
#define A_ROWS2 266
#define ABUF_B (A_ROWS2 * A_STRIDE_B)   // 21280
#define BBUF_B (11 * 32 * 40 * 2)       // 28160
#define ARING_OFF HDR_B
#define B0_OFF (ARING_OFF + 4 * ABUF_B) // 85376
#define B1_OFF (B0_OFF + BBUF_B)        // 113536
#define SM2_BYTES (B1_OFF + BBUF_B)     // 141696

__global__ void __launch_bounds__(512, 1) conv2_mma_kernel(
    const int* __restrict__ seq,
    const float* __restrict__ b2, const float* __restrict__ g2,
    const float* __restrict__ be2, const float* __restrict__ m2,
    const float* __restrict__ v2,
    float* __restrict__ out, int tail_base)
{
    extern __shared__ char smc[];
    uint32_t sb = smem_u32(smc);
    float* hdr = (float*)smc;
    int tid = threadIdx.x, wid = tid >> 5, lane = tid & 31;
    int gid = lane >> 2, tg = lane & 3;
    int row = wid >> 3, wseg = wid & 7;
    int w0 = blockIdx.x * 256;
    int h2a = blockIdx.y * 2;
    int b = blockIdx.z;
    int len1 = (seq[b] - 1) / 2 + 1;
    int npix = min(256, len1 - w0);

    if (w0 == 0 && h2a == 0 && b == 0 && tail_base >= 0 && tid < BB)
        out[tail_base + tid] = (float)((seq[tid] - 1) / 2 + 1);

    if (npix <= 0) {
        int rowsel = tid >> 8, px = tid & 255;
        int h2 = h2a + rowsel;
        if (h2 < H2) {
            float* o = out + ((size_t)(b * 32) * H2 + h2) * W2 + w0 + px;
#pragma unroll
            for (int oc = 0; oc < 32; oc++) o[(size_t)oc * (H2 * W2)] = 0.f;
        }
        return;
    }

    if (tid < 32) {
        float a = g2[tid] * rsqrtf(v2[tid] + EPSV);
        hdr[tid]      = a;
        hdr[32 + tid] = b2[tid] * a + be2[tid] - m2[tid] * a;
    }

    int rlo;
    if (w0 == 0) {
        rlo = 5;
        for (int i = tid; i < 100; i += 512) {
            int s = i / 25, j = i % 25;
            int r = j / 5;
            *(float4*)(smc + ARING_OFF + s * ABUF_B + r * A_STRIDE_B + (j % 5) * 16) =
                make_float4(0.f, 0.f, 0.f, 0.f);
        }
    } else {
        rlo = 0;
        for (int i = tid; i < 100; i += 512) {
            int s = i / 25, j = i % 25;
            int r = 261 + j / 5;
            *(float4*)(smc + ARING_OFF + s * ABUF_B + r * A_STRIDE_B + (j % 5) * 16) =
                make_float4(0.f, 0.f, 0.f, 0.f);
        }
    }

    int act  = min(256, (npix + 15) & ~15);
    int r_hi = min(min(act + 10, 517 - w0), A_ROWS2);

    int khL = max(0, 8 - 2 * h2a);
    int khH = min(20, 90 - 2 * h2a);

    const __half* xbase = g_x1h + ((size_t)(b * H1) * W1 + (w0 - 5)) * 32;

    auto load_A = [&](int ih) {
        if (ih < 0 || ih >= H1) return;
        uint32_t aoff = ARING_OFF + (uint32_t)((ih + 400) & 3) * ABUF_B;
        const __half* src = xbase + (size_t)ih * W1 * 32;
        int chunks = (r_hi - rlo) * 4;
        for (int i = tid; i < chunks; i += 512) {
            int r = rlo + (i >> 2), c = i & 3;
            cp16(sb + aoff + r * A_STRIDE_B + c * 16, src + (size_t)r * 32 + c * 8);
        }
    };
    auto load_Bk = [&](int kh, uint32_t boff) {
        const __half* src = g_w2h + (size_t)kh * (11 * 32 * 40);
        for (int i = tid; i < 1760; i += 512)
            cp16(sb + boff + i * 16, src + i * 8);
    };

    float acc[2][4][4];
#pragma unroll
    for (int mt = 0; mt < 2; mt++)
#pragma unroll
        for (int nt = 0; nt < 4; nt++)
#pragma unroll
            for (int r = 0; r < 4; r++) acc[mt][nt][r] = 0.f;

    int ih0 = 2 * h2a + khL - 10;
    load_A(ih0);
    load_A(ih0 + 1);
    load_A(ih0 + 2);
    load_Bk(khL, B0_OFF);
    cp_commit();

    uint32_t lane_a = (uint32_t)((lane & 15) * A_STRIDE_B + (lane >> 4) * 16);
    uint32_t lane_b = (uint32_t)((lane & 7) * A_STRIDE_B +
                                 ((lane >> 4) * 32) + (((lane >> 3) & 1) * 16));
    int buf = 0;
    int h2r = h2a + row;

    for (int kh = khL; kh <= khH; kh++) {
        cp_wait0();
        __syncthreads();
        if (kh < khH) {
            load_A(2 * h2a + kh - 7);
            load_Bk(kh + 1, buf ? B0_OFF : B1_OFF);
            cp_commit();
        }

        int ihr = 2 * h2a + kh - 10 + 2 * row;
        bool rowok = (ihr >= 0 && ihr < H1) && (h2r < H2);
        if (rowok) {
            uint32_t aoff = sb + ARING_OFF + (uint32_t)((ihr + 400) & 3) * ABUF_B;
            uint32_t bB = sb + (buf ? B1_OFF : B0_OFF) + lane_b;
            for (int kw = 0; kw < 11; kw++) {
                uint32_t bfr[4][4];
                uint32_t bkw = bB + (uint32_t)kw * 2560;
#pragma unroll
                for (int nt = 0; nt < 4; nt++)
                    ldm_x4(bfr[nt], bkw + nt * 640);
#pragma unroll
                for (int mt = 0; mt < 2; mt++) {
                    int pb = wseg * 32 + mt * 16;
                    if (pb >= npix) continue;
                    uint32_t abase = aoff + (uint32_t)(pb + kw) * A_STRIDE_B + lane_a;
#pragma unroll
                    for (int ks = 0; ks < 2; ks++) {
                        uint32_t af[4];
                        ldm_x4(af, abase + ks * 32);
#pragma unroll
                        for (int nt = 0; nt < 4; nt++)
                            mma_f16(acc[mt][nt], af, &bfr[nt][2 * ks]);
                    }
                }
            }
        }
        buf ^= 1;
    }

    if (h2r >= H2) return;
    const float* sa = hdr;
    const float* sc = hdr + 32;
#pragma unroll
    for (int mt = 0; mt < 2; mt++) {
        int p0 = wseg * 32 + mt * 16 + gid;
        int p1 = p0 + 8;
#pragma unroll
        for (int nt = 0; nt < 4; nt++) {
            int oc0 = nt * 8 + 2 * tg;
            int oc1 = oc0 + 1;
            float a0 = sa[oc0], c0 = sc[oc0];
            float a1 = sa[oc1], c1 = sc[oc1];
            float* o0 = out + ((size_t)(b * 32 + oc0) * H2 + h2r) * W2 + w0;
            float* o1 = out + ((size_t)(b * 32 + oc1) * H2 + h2r) * W2 + w0;
            o0[p0] = (p0 < npix) ? fminf(fmaxf(acc[mt][nt][0] * a0 + c0, 0.f), 20.f) : 0.f;
            o1[p0] = (p0 < npix) ? fminf(fmaxf(acc[mt][nt][1] * a1 + c1, 0.f), 20.f) : 0.f;
            o0[p1] = (p1 < npix) ? fminf(fmaxf(acc[mt][nt][2] * a0 + c0, 0.f), 20.f) : 0.f;
            o1[p1] = (p1 < npix) ? fminf(fmaxf(acc[mt][nt][3] * a1 + c1, 0.f), 20.f) : 0.f;
        }
    }
}

extern "C" void kernel_launch(void* const* d_in, const int* in_sizes, int n_in,
                              void* d_out, int out_size) {
    const float* inputs = (const float*)d_in[0];
    const int*   seq    = (const int*)d_in[1];
    const float* w1 = (const float*)d_in[2];
    const float* b1 = (const float*)d_in[3];
    const float* g1 = (const float*)d_in[4];
    const float* be1 = (const float*)d_in[5];
    const float* m1 = (const float*)d_in[6];
    const float* v1 = (const float*)d_in[7];
    const float* w2 = (const float*)d_in[8];
    const float* b2 = (const float*)d_in[9];
    const float* g2 = (const float*)d_in[10];
    const float* be2 = (const float*)d_in[11];
    const float* m2 = (const float*)d_in[12];
    const float* v2 = (const float*)d_in[13];
    float* out = (float*)d_out;

    cudaFuncSetAttribute(conv1_mma_kernel, cudaFuncAttributeMaxDynamicSharedMemorySize, C1_SM_BYTES);
    cudaFuncSetAttribute(conv2_mma_kernel, cudaFuncAttributeMaxDynamicSharedMemorySize, SM2_BYTES);

    {
        int total = BB * H0 * C1_ROW_H;
        prep_kernel<<<(total + 255) / 256, 256>>>(inputs, w1, w2);
    }
    {
        dim3 grid(2, (H1 + 1) / 2, BB);
        conv1_mma_kernel<<<grid, 512, C1_SM_BYTES>>>(seq, b1, g1, be1, m1, v1);
    }
    {
        const int xsize = BB * 32 * H2 * W2;
        int tail_base = (out_size >= xsize + BB) ? xsize : -1;
        dim3 grid(2, (H2 + 1) / 2, BB);
        conv2_mma_kernel<<<grid, 512, SM2_BYTES>>>(seq, b2, g2, be2, m2, v2,
                                                   out, tail_base);
    }
}

// round 16
// speedup vs baseline: 1.0369x; 1.0369x over previous
#include <cuda_runtime.h>
#include <cuda_fp16.h>
#include <math.h>
#include <stdint.h>

#define BB 32
#define H0 161
#define W0 1024
#define H1 81
#define W1 512
#define H2 41
#define W2 512
#define EPSV 1e-5f

// x1 scratch: channels-last fp16 [b][h1][w][ic]
__device__ __half g_x1h[BB * H1 * W1 * 32];
// conv2 weights fp16: [kh][kw][oc][40 pad]
__device__ __half g_w2h[21 * 11 * 32 * 40];
// conv1 input, fp16, shifted rows: [b][ih][t], S[t]=in[t-5]
#define C1_ROW_H 1056
__device__ __half g_in_h[BB * H0 * C1_ROW_H];
// conv1 weights fp16: [kh][oc][18]
__device__ __half g_w1h[41 * 32 * 18];

// ---------------------------------------------------------------------------
__device__ __forceinline__ uint32_t smem_u32(const void* p) {
    uint32_t a;
    asm("{ .reg .u64 t; cvta.to.shared.u64 t, %1; cvt.u32.u64 %0, t; }"
        : "=r"(a) : "l"(p));
    return a;
}
__device__ __forceinline__ void cp16(uint32_t dst, const void* src) {
    asm volatile("cp.async.ca.shared.global [%0], [%1], 16;"
                 :: "r"(dst), "l"(src) : "memory");
}
__device__ __forceinline__ void cp_commit() {
    asm volatile("cp.async.commit_group;" ::: "memory");
}
__device__ __forceinline__ void cp_wait0() {
    asm volatile("cp.async.wait_group 0;" ::: "memory");
}
__device__ __forceinline__ void ldm_x4(uint32_t* a, uint32_t addr) {
    asm volatile("ldmatrix.sync.aligned.m8n8.x4.shared.b16 {%0,%1,%2,%3}, [%4];"
                 : "=r"(a[0]), "=r"(a[1]), "=r"(a[2]), "=r"(a[3]) : "r"(addr));
}
__device__ __forceinline__ void mma_f16(float* d, const uint32_t* a,
                                        const uint32_t* b) {
    asm volatile(
        "mma.sync.aligned.m16n8k16.row.col.f32.f16.f16.f32 "
        "{%0,%1,%2,%3}, {%4,%5,%6,%7}, {%8,%9}, {%0,%1,%2,%3};"
        : "+f"(d[0]), "+f"(d[1]), "+f"(d[2]), "+f"(d[3])
        : "r"(a[0]), "r"(a[1]), "r"(a[2]), "r"(a[3]), "r"(b[0]), "r"(b[1]));
}

// ---------------------------------------------------------------------------
// Kernel 0: merged prep. Input convert vectorized: 8 halves per thread,
// uint4 store. w1/w2 packs unchanged.
// ---------------------------------------------------------------------------
#define C1_ROW8 (C1_ROW_H / 8)   // 132
__global__ void prep_kernel(const float* __restrict__ in,
                            const float* __restrict__ w1,
                            const float* __restrict__ w2) {
    int i = blockIdx.x * 256 + threadIdx.x;
    const int total8 = BB * H0 * C1_ROW8;
    if (i < total8) {
        int c8 = i % C1_ROW8;
        int r  = i / C1_ROW8;
        int t0 = c8 * 8;
        const float* src = in + (size_t)r * W0;
        __half h[8];
#pragma unroll
        for (int j = 0; j < 8; j++) {
            int s = t0 + j - 5;
            float v = 0.f;
            if ((unsigned)s < W0) v = src[s];
            h[j] = __float2half_rn(v);
        }
        *(uint4*)(g_in_h + (size_t)r * C1_ROW_H + t0) = *(const uint4*)h;
    }
    if (i < 41 * 32 * 18) {
        int k = i % 18;
        int t = i / 18;
        int oc = t & 31;
        int kh = t >> 5;
        float v = (k < 11) ? w1[oc * 451 + kh * 11 + k] : 0.f;
        g_w1h[i] = __float2half_rn(v);
    }
    if (i < 21 * 11 * 32 * 40) {
        int ic = i % 40;
        int t = i / 40;
        int oc = t & 31;
        t >>= 5;
        int kw = t % 11;
        int kh = t / 11;
        float v = (ic < 32) ? w2[((oc * 32 + ic) * 21 + kh) * 11 + kw] : 0.f;
        g_w2h[i] = __float2half_rn(v);
    }
}

// ---------------------------------------------------------------------------
// Kernel 1: conv1 fp16 mma, HALF-ROW CTAs (exact 678us R13 shape:
// 256 thr / 8 warps, mt=2, 2 CTAs/SM, barrier-free mainloop), with the
// R14-verified 16-px halo zero on dead halves (conv2 reads at most px 260).
// ---------------------------------------------------------------------------
#define C1_HDR 256
#define C1_W_OFF C1_HDR
#define C1_W_BYTES (41 * 32 * 18 * 2)
#define C1_SM_BYTES (C1_W_OFF + C1_W_BYTES)

__global__ void __launch_bounds__(256, 2) conv1_mma_kernel(
    const int* __restrict__ seq,
    const float* __restrict__ b1, const float* __restrict__ g1,
    const float* __restrict__ be1, const float* __restrict__ m1,
    const float* __restrict__ v1)
{
    extern __shared__ char smc[];
    uint32_t sb = smem_u32(smc);
    float* hdr = (float*)smc;
    int tid = threadIdx.x, wid = tid >> 5, lane = tid & 31;
    int gid = lane >> 2, tg = lane & 3;
    int w0 = blockIdx.x * 256;
    int h1 = blockIdx.y, b = blockIdx.z;
    int len1 = (seq[b] - 1) / 2 + 1;
    int npix = min(256, len1 - w0);

    __half* xb = g_x1h + ((size_t)(b * H1 + h1) * W1 + w0) * 32;

    // Dead half: only the 16-px halo is ever read downstream -> 128 float4.
    if (npix <= 0) {
        if (tid < 128)
            ((float4*)xb)[tid] = make_float4(0.f, 0.f, 0.f, 0.f);
        return;
    }

    if (tid < 32) {
        float a = g1[tid] * rsqrtf(v1[tid] + EPSV);
        hdr[tid]      = a;
        hdr[32 + tid] = b1[tid] * a + be1[tid] - m1[tid] * a;
    }
    for (int i = tid; i < C1_W_BYTES / 16; i += 256)
        cp16(sb + C1_W_OFF + i * 16, (const char*)g_w1h + i * 16);
    cp_commit();
    cp_wait0();
    __syncthreads();   // the ONLY pre-epilogue barrier

    int khL = max(0, 20 - 2 * h1);
    int khH = min(40, 180 - 2 * h1);
    const char* inb =
        (const char*)(g_in_h + (size_t)(b * H0 + 2 * h1 - 20) * C1_ROW_H);

    float acc[2][4][4];
#pragma unroll
    for (int mt = 0; mt < 2; mt++)
#pragma unroll
        for (int nt = 0; nt < 4; nt++)
#pragma unroll
            for (int r = 0; r < 4; r++) acc[mt][nt][r] = 0.f;

    int lofs = 4 * (gid + tg);

#pragma unroll 2
    for (int kh = khL; kh <= khH; kh++) {
        uint32_t bf[4][2];
        const char* wk = smc + C1_W_OFF + kh * (32 * 18 * 2);
#pragma unroll
        for (int nt = 0; nt < 4; nt++) {
            const char* q = wk + (nt * 8 + gid) * 36 + tg * 4;
            bf[nt][0] = *(const uint32_t*)q;
            bf[nt][1] = *(const uint32_t*)(q + 16);
        }
        const char* arow = inb + (size_t)kh * (C1_ROW_H * 2);
#pragma unroll
        for (int mt = 0; mt < 2; mt++) {
            int pb = wid * 32 + mt * 16;
            if (pb >= npix) continue;
            const char* ab = arow + 4 * (w0 + pb) + lofs;
            uint32_t af[4];
            af[0] = *(const uint32_t*)(ab);
            af[1] = *(const uint32_t*)(ab + 32);
            af[2] = *(const uint32_t*)(ab + 16);
            af[3] = *(const uint32_t*)(ab + 48);
#pragma unroll
            for (int nt = 0; nt < 4; nt++)
                mma_f16(acc[mt][nt], af, bf[nt]);
        }
    }

    const float* sa = hdr;
    const float* sc = hdr + 32;
#pragma unroll
    for (int mt = 0; mt < 2; mt++) {
        int p0 = wid * 32 + mt * 16 + gid;
        int p1 = p0 + 8;
#pragma unroll
        for (int nt = 0; nt < 4; nt++) {
            int oc0 = nt * 8 + 2 * tg;
            float a0 = sa[oc0], c0 = sc[oc0];
            float a1 = sa[oc0 + 1], c1 = sc[oc0 + 1];
            float y0 = 0.f, y1 = 0.f, y2 = 0.f, y3 = 0.f;
            if (p0 < npix) {
                y0 = fminf(fmaxf(acc[mt][nt][0] * a0 + c0, 0.f), 20.f);
                y1 = fminf(fmaxf(acc[mt][nt][1] * a1 + c1, 0.f), 20.f);
            }
            if (p1 < npix) {
                y2 = fminf(fmaxf(acc[mt][nt][2] * a0 + c0, 0.f), 20.f);
                y3 = fminf(fmaxf(acc[mt][nt][3] * a1 + c1, 0.f), 20.f);
            }
            *(__half2*)(xb + (size_t)p0 * 32 + oc0) =
                __halves2half2(__float2half_rn(y0), __float2half_rn(y1));
            *(__half2*)(xb + (size_t)p1 * 32 + oc0) =
                __halves2half2(__float2half_rn(y2), __float2half_rn(y3));
        }
    }
}

// ---------------------------------------------------------------------------
// Kernel 2: conv2 fp16 mma, TWO h2 rows per CTA (byte-identical to the
// 678us build).
// ---------------------------------------------------------------------------
#define HDR_B 256
#define A_STRIDE_B 80
#define A_ROWS2 266
#define ABUF_B (A_ROWS2 * A_STRIDE_B)   // 21280
#define BBUF_B (11 * 32 * 40 * 2)       // 28160
#define ARING_OFF HDR_B
#define B0_OFF (ARING_OFF + 4 * ABUF_B) // 85376
#define B1_OFF (B0_OFF + BBUF_B)        // 113536
#define SM2_BYTES (B1_OFF + BBUF_B)     // 141696

__global__ void __launch_bounds__(512, 1) conv2_mma_kernel(
    const int* __restrict__ seq,
    const float* __restrict__ b2, const float* __restrict__ g2,
    const float* __restrict__ be2, const float* __restrict__ m2,
    const float* __restrict__ v2,
    float* __restrict__ out, int tail_base)
{
    extern __shared__ char smc[];
    uint32_t sb = smem_u32(smc);
    float* hdr = (float*)smc;
    int tid = threadIdx.x, wid = tid >> 5, lane = tid & 31;
    int gid = lane >> 2, tg = lane & 3;
    int row = wid >> 3, wseg = wid & 7;
    int w0 = blockIdx.x * 256;
    int h2a = blockIdx.y * 2;
    int b = blockIdx.z;
    int len1 = (seq[b] - 1) / 2 + 1;
    int npix = min(256, len1 - w0);

    if (w0 == 0 && h2a == 0 && b == 0 && tail_base >= 0 && tid < BB)
        out[tail_base + tid] = (float)((seq[tid] - 1) / 2 + 1);

    if (npix <= 0) {
        int rowsel = tid >> 8, px = tid & 255;
        int h2 = h2a + rowsel;
        if (h2 < H2) {
            float* o = out + ((size_t)(b * 32) * H2 + h2) * W2 + w0 + px;
#pragma unroll
            for (int oc = 0; oc < 32; oc++) o[(size_t)oc * (H2 * W2)] = 0.f;
        }
        return;
    }

    if (tid < 32) {
        float a = g2[tid] * rsqrtf(v2[tid] + EPSV);
        hdr[tid]      = a;
        hdr[32 + tid] = b2[tid] * a + be2[tid] - m2[tid] * a;
    }

    int rlo;
    if (w0 == 0) {
        rlo = 5;
        for (int i = tid; i < 100; i += 512) {
            int s = i / 25, j = i % 25;
            int r = j / 5;
            *(float4*)(smc + ARING_OFF + s * ABUF_B + r * A_STRIDE_B + (j % 5) * 16) =
                make_float4(0.f, 0.f, 0.f, 0.f);
        }
    } else {
        rlo = 0;
        for (int i = tid; i < 100; i += 512) {
            int s = i / 25, j = i % 25;
            int r = 261 + j / 5;
            *(float4*)(smc + ARING_OFF + s * ABUF_B + r * A_STRIDE_B + (j % 5) * 16) =
                make_float4(0.f, 0.f, 0.f, 0.f);
        }
    }

    int act  = min(256, (npix + 15) & ~15);
    int r_hi = min(min(act + 10, 517 - w0), A_ROWS2);

    int khL = max(0, 8 - 2 * h2a);
    int khH = min(20, 90 - 2 * h2a);

    const __half* xbase = g_x1h + ((size_t)(b * H1) * W1 + (w0 - 5)) * 32;

    auto load_A = [&](int ih) {
        if (ih < 0 || ih >= H1) return;
        uint32_t aoff = ARING_OFF + (uint32_t)((ih + 400) & 3) * ABUF_B;
        const __half* src = xbase + (size_t)ih * W1 * 32;
        int chunks = (r_hi - rlo) * 4;
        for (int i = tid; i < chunks; i += 512) {
            int r = rlo + (i >> 2), c = i & 3;
            cp16(sb + aoff + r * A_STRIDE_B + c * 16, src + (size_t)r * 32 + c * 8);
        }
    };
    auto load_Bk = [&](int kh, uint32_t boff) {
        const __half* src = g_w2h + (size_t)kh * (11 * 32 * 40);
        for (int i = tid; i < 1760; i += 512)
            cp16(sb + boff + i * 16, src + i * 8);
    };

    float acc[2][4][4];
#pragma unroll
    for (int mt = 0; mt < 2; mt++)
#pragma unroll
        for (int nt = 0; nt < 4; nt++)
#pragma unroll
            for (int r = 0; r < 4; r++) acc[mt][nt][r] = 0.f;

    int ih0 = 2 * h2a + khL - 10;
    load_A(ih0);
    load_A(ih0 + 1);
    load_A(ih0 + 2);
    load_Bk(khL, B0_OFF);
    cp_commit();

    uint32_t lane_a = (uint32_t)((lane & 15) * A_STRIDE_B + (lane >> 4) * 16);
    uint32_t lane_b = (uint32_t)((lane & 7) * A_STRIDE_B +
                                 ((lane >> 4) * 32) + (((lane >> 3) & 1) * 16));
    int buf = 0;
    int h2r = h2a + row;

    for (int kh = khL; kh <= khH; kh++) {
        cp_wait0();
        __syncthreads();
        if (kh < khH) {
            load_A(2 * h2a + kh - 7);
            load_Bk(kh + 1, buf ? B0_OFF : B1_OFF);
            cp_commit();
        }

        int ihr = 2 * h2a + kh - 10 + 2 * row;
        bool rowok = (ihr >= 0 && ihr < H1) && (h2r < H2);
        if (rowok) {
            uint32_t aoff = sb + ARING_OFF + (uint32_t)((ihr + 400) & 3) * ABUF_B;
            uint32_t bB = sb + (buf ? B1_OFF : B0_OFF) + lane_b;
            for (int kw = 0; kw < 11; kw++) {
                uint32_t bfr[4][4];
                uint32_t bkw = bB + (uint32_t)kw * 2560;
#pragma unroll
                for (int nt = 0; nt < 4; nt++)
                    ldm_x4(bfr[nt], bkw + nt * 640);
#pragma unroll
                for (int mt = 0; mt < 2; mt++) {
                    int pb = wseg * 32 + mt * 16;
                    if (pb >= npix) continue;
                    uint32_t abase = aoff + (uint32_t)(pb + kw) * A_STRIDE_B + lane_a;
#pragma unroll
                    for (int ks = 0; ks < 2; ks++) {
                        uint32_t af[4];
                        ldm_x4(af, abase + ks * 32);
#pragma unroll
                        for (int nt = 0; nt < 4; nt++)
                            mma_f16(acc[mt][nt], af, &bfr[nt][2 * ks]);
                    }
                }
            }
        }
        buf ^= 1;
    }

    if (h2r >= H2) return;
    const float* sa = hdr;
    const float* sc = hdr + 32;
#pragma unroll
    for (int mt = 0; mt < 2; mt++) {
        int p0 = wseg * 32 + mt * 16 + gid;
        int p1 = p0 + 8;
#pragma unroll
        for (int nt = 0; nt < 4; nt++) {
            int oc0 = nt * 8 + 2 * tg;
            int oc1 = oc0 + 1;
            float a0 = sa[oc0], c0 = sc[oc0];
            float a1 = sa[oc1], c1 = sc[oc1];
            float* o0 = out + ((size_t)(b * 32 + oc0) * H2 + h2r) * W2 + w0;
            float* o1 = out + ((size_t)(b * 32 + oc1) * H2 + h2r) * W2 + w0;
            o0[p0] = (p0 < npix) ? fminf(fmaxf(acc[mt][nt][0] * a0 + c0, 0.f), 20.f) : 0.f;
            o1[p0] = (p0 < npix) ? fminf(fmaxf(acc[mt][nt][1] * a1 + c1, 0.f), 20.f) : 0.f;
            o0[p1] = (p1 < npix) ? fminf(fmaxf(acc[mt][nt][2] * a0 + c0, 0.f), 20.f) : 0.f;
            o1[p1] = (p1 < npix) ? fminf(fmaxf(acc[mt][nt][3] * a1 + c1, 0.f), 20.f) : 0.f;
        }
    }
}

extern "C" void kernel_launch(void* const* d_in, const int* in_sizes, int n_in,
                              void* d_out, int out_size) {
    const float* inputs = (const float*)d_in[0];
    const int*   seq    = (const int*)d_in[1];
    const float* w1 = (const float*)d_in[2];
    const float* b1 = (const float*)d_in[3];
    const float* g1 = (const float*)d_in[4];
    const float* be1 = (const float*)d_in[5];
    const float* m1 = (const float*)d_in[6];
    const float* v1 = (const float*)d_in[7];
    const float* w2 = (const float*)d_in[8];
    const float* b2 = (const float*)d_in[9];
    const float* g2 = (const float*)d_in[10];
    const float* be2 = (const float*)d_in[11];
    const float* m2 = (const float*)d_in[12];
    const float* v2 = (const float*)d_in[13];
    float* out = (float*)d_out;

    cudaFuncSetAttribute(conv1_mma_kernel, cudaFuncAttributeMaxDynamicSharedMemorySize, C1_SM_BYTES);
    cudaFuncSetAttribute(conv2_mma_kernel, cudaFuncAttributeMaxDynamicSharedMemorySize, SM2_BYTES);

    {
        int total8 = BB * H0 * C1_ROW8;
        int total = 21 * 11 * 32 * 40;   // largest remaining range
        int n = total8 > total ? total8 : total;
        prep_kernel<<<(n + 255) / 256, 256>>>(inputs, w1, w2);
    }
    {
        dim3 grid(2, H1, BB);
        conv1_mma_kernel<<<grid, 256, C1_SM_BYTES>>>(seq, b1, g1, be1, m1, v1);
    }
    {
        const int xsize = BB * 32 * H2 * W2;
        int tail_base = (out_size >= xsize + BB) ? xsize : -1;
        dim3 grid(2, (H2 + 1) / 2, BB);
        conv2_mma_kernel<<<grid, 512, SM2_BYTES>>>(seq, b2, g2, be2, m2, v2,
                                                   out, tail_base);
    }
}